// round 16
// baseline (speedup 1.0000x reference)
#include <cuda_runtime.h>
#include <stdint.h>

// SmoothLDDTLoss — b=2, n=4096. Fused single kernel.
// R13 resubmit #2 (broker infra failure twice; kernel never executed):
// 2-i register blocking (i-tile 128, j-tile 64, 64 threads): each LDS
// group serves 4 pairs; 4 independent MUFU chains per iter.
// Symmetric-polynomial sigmoid sum (P/Q Horner); expansion-form distances
// on sqrt(2)*LOG2E-scaled coords; coords_mask via +1e30 poison;
// 1 rcp per 2 pairs; FFMA-mask accumulation.

#define TJ 64            // j-tile (= threads per block)
#define TI 128           // i-tile (2 per thread)
#define QN (TJ / 2)

__device__ double       g_sum[2];
__device__ double       g_cnt[2];
__device__ unsigned int g_done;

__device__ __forceinline__ float fsqrt_ap(float x) { float r; asm("sqrt.approx.f32 %0, %1;" : "=f"(r) : "f"(x)); return r; }
__device__ __forceinline__ float frcp_ap (float x) { float r; asm("rcp.approx.f32 %0, %1;"  : "=f"(r) : "f"(x)); return r; }
__device__ __forceinline__ float fex2_ap (float x) { float r; asm("ex2.approx.f32 %0, %1;"  : "=f"(r) : "f"(x)); return r; }

constexpr float SC    = 2.04022209793536f;    // sqrt(2)*LOG2E
constexpr float L2C   = 2.08136899f;          // LOG2E^2
constexpr float CLAMPD= 14.4269504088896f;    // 10*LOG2E
constexpr float R225  = 225.0f * L2C;
constexpr float R900  = 900.0f * L2C;

// sum_k 1/(1+c_k e) = PP(e)/QQ(e), c = {e^-.5, e^-1, e^-2, e^-4}
constexpr float ES1 = 1.12806064f;
constexpr float ES2 = 0.37532785f;
constexpr float ES3 = 0.03669949f;
constexpr float ES4 = 0.000553084f;
constexpr float PC1 = 3.0f * ES1;
constexpr float PC2 = 2.0f * ES2;

struct __align__(16) SmemG {
    float4 Pa, Ta, Pb, Tb;   // (px,py,pz,sqp)/(tx,ty,tz,sqt) for j0,j1
    float2 R;                // (r2_j0, r2_j1)
    float2 pad;
};

struct IPoint {
    float nx, ny, nz;        // -scaled pred coords
    float mx, my, mz;        // -scaled true coords
    float sqp, sqt;          // scaled |p|^2, |t|^2 (poisoned if masked)
    bool  nuc;
    int   ig;
};

__device__ __forceinline__ void pair_eps(float dt2, float dp2, float& num, float& den)
{
    float st = fsqrt_ap(dt2);
    float sp = fsqrt_ap(dp2);
    float diff = fminf(fabsf(st - sp), CLAMPD);
    float e  = fex2_ap(diff);
    num = fmaf(fmaf(fmaf(ES3, e, PC2), e, PC1), e, 4.0f);
    den = fmaf(fmaf(fmaf(fmaf(ES4, e, ES3), e, ES2), e, ES1), e, 1.0f);
}

template<bool DIAG>
__device__ __forceinline__ void do_i(
    const IPoint& I, const SmemG* g, int jA, int jB,
    float& asum, float& acnt)
{
    float4 Pa = g->Pa, Ta = g->Ta;
    float4 Pb = g->Pb, Tb = g->Tb;
    float2 R  = g->R;

    float dpA = fmaf(I.nx, Pa.x, fmaf(I.ny, Pa.y, fmaf(I.nz, Pa.z, I.sqp + Pa.w)));
    float dtA = fmaf(I.mx, Ta.x, fmaf(I.my, Ta.y, fmaf(I.mz, Ta.z, I.sqt + Ta.w)));
    float dpB = fmaf(I.nx, Pb.x, fmaf(I.ny, Pb.y, fmaf(I.nz, Pb.z, I.sqp + Pb.w)));
    float dtB = fmaf(I.mx, Tb.x, fmaf(I.my, Tb.y, fmaf(I.mz, Tb.z, I.sqt + Tb.w)));

    float numA, denA, numB, denB;
    pair_eps(dtA, dpA, numA, denA);
    pair_eps(dtB, dpB, numB, denB);

    float r    = frcp_ap(denA * denB);
    float epsA = numA * (r * denB);
    float epsB = numB * (r * denA);

    float R2A = I.nuc ? R.x : R225;
    float R2B = I.nuc ? R.y : R225;
    bool vA = dtA < R2A;
    bool vB = dtB < R2B;
    if (DIAG) {
        vA = vA && (jA > I.ig);
        vB = vB && (jB > I.ig);
    }
    float mA = vA ? 1.0f : 0.0f;
    float mB = vB ? 1.0f : 0.0f;
    asum = fmaf(epsA, mA, asum);
    asum = fmaf(epsB, mB, asum);
    acnt += mA + mB;
}

__device__ __forceinline__ void load_i(
    IPoint& I, int ig, int n, long base,
    const float* pred, const float* truec,
    const uint8_t* is_dna, const uint8_t* is_rna, const uint8_t* cmask)
{
    I.nx = I.ny = I.nz = I.mx = I.my = I.mz = 0.f;
    I.sqp = 0.f; I.sqt = 1e30f; I.nuc = false; I.ig = ig;
    if (ig < n) {
        long idx = (base + ig) * 3;
        float ax = pred[idx + 0] * SC, ay = pred[idx + 1] * SC, az = pred[idx + 2] * SC;
        float bx = truec[idx + 0] * SC, by = truec[idx + 1] * SC, bz = truec[idx + 2] * SC;
        I.sqp = 0.5f * fmaf(ax, ax, fmaf(ay, ay, az * az));
        I.sqt = 0.5f * fmaf(bx, bx, fmaf(by, by, bz * bz));
        I.nx = -ax; I.ny = -ay; I.nz = -az;
        I.mx = -bx; I.my = -by; I.mz = -bz;
        I.nuc = (__ldg(&is_dna[base + ig]) | __ldg(&is_rna[base + ig])) != 0;
        if (!__ldg(&cmask[base + ig])) I.sqt += 1e30f;
    }
}

__global__ void __launch_bounds__(TJ, 16) lddt_fused_kernel(
    const float* __restrict__ pred,
    const float* __restrict__ truec,
    const uint8_t* __restrict__ is_dna,
    const uint8_t* __restrict__ is_rna,
    const uint8_t* __restrict__ cmask,
    float* __restrict__ out,
    int n, int ntJ, unsigned int total_blocks)
{
    // decode blockIdx.x -> (ti, tj): row ti has j-tiles tj in [2*ti, ntJ)
    // offset(ti) = ti*(ntJ+1-ti)
    int t = blockIdx.x;
    float M = (float)(ntJ + 1);
    float s = sqrtf(fmaf(M, M, -4.0f * (float)t));
    int ti = (int)floorf(0.5f * (M - s));
    if (ti < 0) ti = 0;
    #pragma unroll
    for (int k = 0; k < 2; k++) {
        int off  = ti * (ntJ + 1 - ti);
        int offn = (ti + 1) * (ntJ - ti);
        if (t < off)        ti--;
        else if (t >= offn) ti++;
    }
    int off = ti * (ntJ + 1 - ti);
    int tj = 2 * ti + (t - off);
    if (tj < 0) tj = 0;
    if (tj > ntJ - 1) tj = ntJ - 1;
    const bool diag = (tj <= 2 * ti + 1);   // j-tile overlaps i-tile rows

    const int b = blockIdx.y;
    const int tid = threadIdx.x;
    const long base = (long)b * n;

    __shared__ SmemG W[QN];

    // ---- fill j tile (TJ points) ----
    {
        int jg = tj * TJ + tid;
        float4 P = make_float4(0.f, 0.f, 0.f, 0.f);
        float4 T = make_float4(0.f, 0.f, 0.f, 1e30f);
        float r2 = R225;
        if (jg < n) {
            long idx = (base + jg) * 3;
            P.x = pred[idx + 0] * SC; P.y = pred[idx + 1] * SC; P.z = pred[idx + 2] * SC;
            T.x = truec[idx + 0] * SC; T.y = truec[idx + 1] * SC; T.z = truec[idx + 2] * SC;
            P.w = 0.5f * fmaf(P.x, P.x, fmaf(P.y, P.y, P.z * P.z));
            T.w = 0.5f * fmaf(T.x, T.x, fmaf(T.y, T.y, T.z * T.z));
            bool nuc = (__ldg(&is_dna[base + jg]) | __ldg(&is_rna[base + jg])) != 0;
            r2 = nuc ? R900 : R225;
            if (!__ldg(&cmask[base + jg])) T.w += 1e30f;
        }
        int q = tid >> 1, l = tid & 1;
        if (l == 0) { W[q].Pa = P; W[q].Ta = T; W[q].R.x = r2; }
        else        { W[q].Pb = P; W[q].Tb = T; W[q].R.y = r2; }
    }
    __syncthreads();

    // ---- two i points per thread ----
    IPoint I0, I1;
    load_i(I0, ti * TI + tid,      n, base, pred, truec, is_dna, is_rna, cmask);
    load_i(I1, ti * TI + TJ + tid, n, base, pred, truec, is_dna, is_rna, cmask);

    float as0 = 0.f, ac0 = 0.f, as1 = 0.f, ac1 = 0.f;
    const int jbase = tj * TJ;

    if (diag) {
        #pragma unroll 2
        for (int q = 0; q < QN; q++) {
            int jA = jbase + 2 * q, jB = jA + 1;
            do_i<true>(I0, W + q, jA, jB, as0, ac0);
            do_i<true>(I1, W + q, jA, jB, as1, ac1);
        }
    } else {
        #pragma unroll 2
        for (int q = 0; q < QN; q++) {
            do_i<false>(I0, W + q, 0, 0, as0, ac0);
            do_i<false>(I1, W + q, 0, 0, as1, ac1);
        }
    }

    float acc_sum = as0 + as1;
    float acc_cnt = ac0 + ac1;

    // ---- block reduce (64 threads = 2 warps) ----
    #pragma unroll
    for (int o = 16; o > 0; o >>= 1) {
        acc_sum += __shfl_down_sync(0xFFFFFFFFu, acc_sum, o);
        acc_cnt += __shfl_down_sync(0xFFFFFFFFu, acc_cnt, o);
    }
    __shared__ float ws[2], wc[2];
    if ((tid & 31) == 0) { ws[tid >> 5] = acc_sum; wc[tid >> 5] = acc_cnt; }
    __syncthreads();

    if (tid == 0) {
        float S = ws[0] + ws[1];
        float C = wc[0] + wc[1];
        atomicAdd(&g_sum[b], (double)S * 0.25);
        atomicAdd(&g_cnt[b], (double)C);

        __threadfence();
        unsigned int done = atomicAdd(&g_done, 1u);
        if (done == total_blocks - 1u) {
            volatile double* vs = g_sum;
            volatile double* vc = g_cnt;
            double c0 = vc[0]; if (c0 < 1.0) c0 = 1.0;
            double c1 = vc[1]; if (c1 < 1.0) c1 = 1.0;
            double l0 = vs[0] / c0;
            double l1 = vs[1] / c1;
            out[0] = (float)(1.0 - 0.5 * (l0 + l1));
            g_sum[0] = 0.0; g_sum[1] = 0.0;
            g_cnt[0] = 0.0; g_cnt[1] = 0.0;
            __threadfence();
            g_done = 0u;
        }
    }
}

extern "C" void kernel_launch(void* const* d_in, const int* in_sizes, int n_in,
                              void* d_out, int out_size)
{
    const float*   pred  = (const float*)d_in[0];
    const float*   truec = (const float*)d_in[1];
    const uint8_t* dna   = (const uint8_t*)d_in[2];
    const uint8_t* rna   = (const uint8_t*)d_in[3];
    const uint8_t* cm    = (const uint8_t*)d_in[4];

    const int B = 2;
    const int n = in_sizes[2] / B;
    const int ntI = (n + TI - 1) / TI;
    const int ntJ = (n + TJ - 1) / TJ;
    int npairs = 0;
    for (int ti = 0; ti < ntI; ti++) {
        int len = ntJ - 2 * ti;
        if (len > 0) npairs += len;
    }

    dim3 grid(npairs, B);
    lddt_fused_kernel<<<grid, TJ>>>(pred, truec, dna, rna, cm,
                                    (float*)d_out, n, ntJ,
                                    (unsigned int)(npairs * B));
}